// round 11
// baseline (speedup 1.0000x reference)
#include <cuda_runtime.h>
#include <cuda_bf16.h>
#include <cstdint>

#define T_SEQ 2048
#define CH    1024
#define NH    16
#define HD    64
#define BATCH 2
#define BT    (BATCH*T_SEQ)   // 4096
#define BHCNT (BATCH*NH)      // 32

typedef __nv_bfloat16 bf16;

// ---------------- scratch (no cudaMalloc allowed) ----------------
__device__ bf16 g_x_hi[(size_t)BT * CH],    g_x_lo[(size_t)BT * CH];
__device__ bf16 g_wq_hi[(size_t)3*CH*CH],   g_wq_lo[(size_t)3*CH*CH];
__device__ bf16 g_wo_hi[(size_t)CH*CH],     g_wo_lo[(size_t)CH*CH];
__device__ bf16 g_qkv_hi[(size_t)3*BHCNT*T_SEQ*HD], g_qkv_lo[(size_t)3*BHCNT*T_SEQ*HD];
__device__ bf16 g_at_hi[(size_t)BT * CH],   g_at_lo[(size_t)BT * CH];

// ---------------- helpers ----------------
__device__ __forceinline__ uint32_t smem_u32(const void* p) {
    uint32_t a;
    asm("{ .reg .u64 t; cvta.to.shared.u64 t, %1; cvt.u32.u64 %0, t; }"
        : "=r"(a) : "l"(p));
    return a;
}
#define CP_ASYNC16(dst, src) \
    asm volatile("cp.async.cg.shared.global [%0], [%1], 16;" :: "r"(dst), "l"(src))
#define CP_COMMIT() asm volatile("cp.async.commit_group;" ::: "memory")
#define CP_WAIT1()  asm volatile("cp.async.wait_group 1;" ::: "memory")
#define CP_WAIT2()  asm volatile("cp.async.wait_group 2;" ::: "memory")

__device__ __forceinline__ void ldsm4(uint32_t& r0, uint32_t& r1,
                                      uint32_t& r2, uint32_t& r3, uint32_t addr) {
    asm volatile("ldmatrix.sync.aligned.m8n8.x4.shared.b16 {%0,%1,%2,%3}, [%4];"
                 : "=r"(r0), "=r"(r1), "=r"(r2), "=r"(r3) : "r"(addr));
}
__device__ __forceinline__ void ldsm4t(uint32_t& r0, uint32_t& r1,
                                       uint32_t& r2, uint32_t& r3, uint32_t addr) {
    asm volatile("ldmatrix.sync.aligned.m8n8.x4.trans.shared.b16 {%0,%1,%2,%3}, [%4];"
                 : "=r"(r0), "=r"(r1), "=r"(r2), "=r"(r3) : "r"(addr));
}
__device__ __forceinline__ void mma16816(float* c, const uint32_t* a,
                                         uint32_t b0, uint32_t b1) {
    asm volatile("mma.sync.aligned.m16n8k16.row.col.f32.bf16.bf16.f32 "
                 "{%0,%1,%2,%3}, {%4,%5,%6,%7}, {%8,%9}, {%0,%1,%2,%3};"
                 : "+f"(c[0]), "+f"(c[1]), "+f"(c[2]), "+f"(c[3])
                 : "r"(a[0]), "r"(a[1]), "r"(a[2]), "r"(a[3]), "r"(b0), "r"(b1));
}

// ---------------------------------------------------------------------------
// Split fp32 -> bf16 hi + lo residual
// ---------------------------------------------------------------------------
__global__ __launch_bounds__(256) void convert_split(
    const float* __restrict__ src, bf16* __restrict__ hi,
    bf16* __restrict__ lo, int n)
{
    int i = (blockIdx.x * 256 + threadIdx.x) * 4;
    if (i >= n) return;
    float4 v = *(const float4*)(src + i);
    __nv_bfloat162 h01 = __floats2bfloat162_rn(v.x, v.y);
    __nv_bfloat162 h23 = __floats2bfloat162_rn(v.z, v.w);
    __nv_bfloat162 l01 = __floats2bfloat162_rn(v.x - __bfloat162float(h01.x),
                                               v.y - __bfloat162float(h01.y));
    __nv_bfloat162 l23 = __floats2bfloat162_rn(v.z - __bfloat162float(h23.x),
                                               v.w - __bfloat162float(h23.y));
    *(__nv_bfloat162*)(hi + i)     = h01;
    *(__nv_bfloat162*)(hi + i + 2) = h23;
    *(__nv_bfloat162*)(lo + i)     = l01;
    *(__nv_bfloat162*)(lo + i + 2) = l23;
}

// ---------------------------------------------------------------------------
// bf16x3 GEMM via mma.sync (NT), 4-stage BK=32 cp.async, XOR swizzle,
// interleaved MMA order (R8 best), 2 CTAs/SM. CTA 128x64, 8 warps (4M x 2N).
// mode 0: write bf16 hi/lo into g_qkv (Q pre-scaled by 0.125)
// mode 1: write fp32 row-major into Cout
// ---------------------------------------------------------------------------
#define GAB 8192                         // A array bytes (128 rows x 64B)
#define GBB 4096                         // B array bytes (64 rows x 64B)
#define G_STAGE (2 * GAB + 2 * GBB)      // 24576
#define GEMM_SMEM (4 * G_STAGE)          // 98304

__device__ __forceinline__ uint32_t gswz(int r, int c16) {
    return (uint32_t)(r * 64 + ((c16 ^ ((r >> 1) & 3)) << 4));
}

__global__ __launch_bounds__(256, 2) void gemm_mma(
    const bf16* __restrict__ Ahi, const bf16* __restrict__ Alo,
    const bf16* __restrict__ Bhi, const bf16* __restrict__ Blo,
    const float* __restrict__ bias, float* __restrict__ Cout,
    int N, int K, int mode)
{
    extern __shared__ __align__(16) bf16 sm[];
    const uint32_t sbase = smem_u32(sm);

    const int tid = threadIdx.x;
    const int lane = tid & 31;
    const int w = tid >> 5;
    const int wm = w & 3;
    const int wn = w >> 2;
    const int m0 = blockIdx.y * 128;
    const int n0 = blockIdx.x * 64;

    const int ar  = tid >> 1;
    const int ac0 = (tid & 1) * 2;
    const int br  = tid >> 2;
    const int bc  = tid & 3;

    auto prefetch = [&](int c) {
        const uint32_t sb = sbase + (c & 3) * G_STAGE;
        const int k0 = c * 32;
#pragma unroll
        for (int j = 0; j < 2; j++) {
            const int c16 = ac0 + j;
            const uint32_t d = sb + gswz(ar, c16);
            const size_t ga = (size_t)(m0 + ar) * K + k0 + c16 * 8;
            CP_ASYNC16(d,       Ahi + ga);
            CP_ASYNC16(d + GAB, Alo + ga);
        }
        {
            const uint32_t d = sb + 2 * GAB + gswz(br, bc);
            const size_t gb = (size_t)(n0 + br) * K + k0 + bc * 8;
            CP_ASYNC16(d,       Bhi + gb);
            CP_ASYNC16(d + GBB, Blo + gb);
        }
    };

    float acc[2][4][4];
#pragma unroll
    for (int mi = 0; mi < 2; mi++)
#pragma unroll
        for (int nt = 0; nt < 4; nt++)
#pragma unroll
            for (int j = 0; j < 4; j++) acc[mi][nt][j] = 0.f;

    prefetch(0); CP_COMMIT();
    prefetch(1); CP_COMMIT();
    prefetch(2); CP_COMMIT();

    const int NC = K / 32;
    for (int c = 0; c < NC; c++) {
        CP_WAIT2();
        __syncthreads();
        if (c + 3 < NC) prefetch(c + 3);
        CP_COMMIT();
        const uint32_t sb = sbase + (c & 3) * G_STAGE;

#pragma unroll
        for (int kc = 0; kc < 2; kc++) {
            const int kk16 = kc * 2;
            uint32_t af[2][2][4];
            const int arow = wm * 32 + (lane & 15);
            const int ac16 = kk16 + (lane >> 4);
#pragma unroll
            for (int mi = 0; mi < 2; mi++) {
                const uint32_t ad = sb + gswz(arow + mi * 16, ac16);
                ldsm4(af[0][mi][0], af[0][mi][1], af[0][mi][2], af[0][mi][3], ad);
                ldsm4(af[1][mi][0], af[1][mi][1], af[1][mi][2], af[1][mi][3],
                      ad + GAB);
            }
            uint32_t bfh[4][2], bfl[4][2];
            const int brow_base = wn * 32 + ((lane >> 4) << 3) + (lane & 7);
            const int bc16 = kk16 + ((lane >> 3) & 1);
#pragma unroll
            for (int p = 0; p < 2; p++) {
                const uint32_t bd = sb + 2 * GAB + gswz(brow_base + p * 16, bc16);
                uint32_t r0, r1, r2, r3;
                ldsm4(r0, r1, r2, r3, bd);
                bfh[2 * p][0] = r0; bfh[2 * p][1] = r1;
                bfh[2 * p + 1][0] = r2; bfh[2 * p + 1][1] = r3;
                ldsm4(r0, r1, r2, r3, bd + GBB);
                bfl[2 * p][0] = r0; bfl[2 * p][1] = r1;
                bfl[2 * p + 1][0] = r2; bfl[2 * p + 1][1] = r3;
            }
#pragma unroll
            for (int mi = 0; mi < 2; mi++)
#pragma unroll
                for (int nt = 0; nt < 4; nt++) {
                    mma16816(acc[mi][nt], af[0][mi], bfh[nt][0], bfh[nt][1]);
                    mma16816(acc[mi][nt], af[1][mi], bfh[nt][0], bfh[nt][1]);
                    mma16816(acc[mi][nt], af[0][mi], bfl[nt][0], bfl[nt][1]);
                }
        }
    }

    // epilogue
#pragma unroll
    for (int mi = 0; mi < 2; mi++) {
        const int rbase = m0 + wm * 32 + mi * 16 + (lane >> 2);
#pragma unroll
        for (int hr = 0; hr < 2; hr++) {
            const int r = rbase + hr * 8;
#pragma unroll
            for (int nt = 0; nt < 4; nt++) {
                const int n = n0 + wn * 32 + nt * 8 + (lane & 3) * 2;
                float2 bb = *(const float2*)&bias[n];
                float f0 = acc[mi][nt][hr * 2 + 0] + bb.x;
                float f1 = acc[mi][nt][hr * 2 + 1] + bb.y;
                if (mode == 0) {
                    const int s = n >> 10;
                    if (s == 0) { f0 *= 0.125f; f1 *= 0.125f; }  // fold 1/sqrt(64) into Q
                    const int b = r >> 11, t = r & 2047;
                    const int hh = (n >> 6) & 15, d = n & 63;
                    __nv_bfloat162 hi2 = __floats2bfloat162_rn(f0, f1);
                    __nv_bfloat162 lo2 = __floats2bfloat162_rn(
                        f0 - __bfloat162float(hi2.x), f1 - __bfloat162float(hi2.y));
                    const size_t o =
                        ((size_t)(s * BHCNT + b * NH + hh) * T_SEQ + t) * HD + d;
                    *(__nv_bfloat162*)&g_qkv_hi[o] = hi2;
                    *(__nv_bfloat162*)&g_qkv_lo[o] = lo2;
                } else {
                    float2 o2 = {f0, f1};
                    *(float2*)&Cout[(size_t)r * N + n] = o2;
                }
            }
        }
    }
}

// ---------------------------------------------------------------------------
// Flash causal attention, bf16x3, 3-stage cp.async K/V pipeline, 2 CTAs/SM.
// Q fragments assembled DIRECTLY FROM GMEM (no Q smem) -> smem 110.6KB.
// BQ=128, BK=64, 8 warps; warp w owns rows [w*16, w*16+16).
// CTAs remapped heavy-first.
// ---------------------------------------------------------------------------
#define FQ 72
#define F_KBYTES (64 * FQ * 2)              // 9216 bytes per K/V array
#define F_STAGE  (4 * F_KBYTES)             // 36864 bytes per stage
#define FLASH_SMEM (3 * F_STAGE)            // 110592

__global__ __launch_bounds__(256, 2) void flash_mma()
{
    extern __shared__ __align__(16) bf16 smf[];
    const uint32_t sbase = smem_u32(smf);

    const int tid = threadIdx.x;
    const int lane = tid & 31;
    const int w = tid >> 5;
    const int qi = (int)gridDim.x - 1 - (int)blockIdx.x;   // heavy tiles first
    const int q0 = qi * 128;
    const int bh = blockIdx.y;

    const bf16* Qh = g_qkv_hi + (size_t)(0 * BHCNT + bh) * T_SEQ * HD;
    const bf16* Ql = g_qkv_lo + (size_t)(0 * BHCNT + bh) * T_SEQ * HD;
    const bf16* Kh = g_qkv_hi + (size_t)(1 * BHCNT + bh) * T_SEQ * HD;
    const bf16* Kl = g_qkv_lo + (size_t)(1 * BHCNT + bh) * T_SEQ * HD;
    const bf16* Vh = g_qkv_hi + (size_t)(2 * BHCNT + bh) * T_SEQ * HD;
    const bf16* Vl = g_qkv_lo + (size_t)(2 * BHCNT + bh) * T_SEQ * HD;

    const int ldr = tid >> 3;
    const int ldc = (tid & 7) * 8;

    auto prefetch_kv = [&](int kt) {
        const uint32_t sb = sbase + (kt % 3) * F_STAGE;
        const int k0 = kt * 64;
#pragma unroll
        for (int it = 0; it < 2; it++) {
            const int r = it * 32 + ldr;
            const uint32_t d = sb + (r * FQ + ldc) * 2;
            const size_t g = (size_t)(k0 + r) * HD + ldc;
            CP_ASYNC16(d,                Kh + g);
            CP_ASYNC16(d + F_KBYTES,     Kl + g);
            CP_ASYNC16(d + 2 * F_KBYTES, Vh + g);
            CP_ASYNC16(d + 3 * F_KBYTES, Vl + g);
        }
    };

    const int ntiles = 2 * qi + 2;
    prefetch_kv(0); CP_COMMIT();
    prefetch_kv(1); CP_COMMIT();

    // Build Q fragments directly from gmem (m16k16 A-frag layout):
    //   a0=(r0,c0) a1=(r0+8,c0) a2=(r0,c0+8) a3=(r0+8,c0+8), 2-elem pairs.
    uint32_t qf[2][4][4];
    {
        const int qr = q0 + w * 16 + (lane >> 2);
        const int cb0 = (lane & 3) * 2;
#pragma unroll
        for (int kc = 0; kc < 4; kc++) {
            const int cb = kc * 16 + cb0;
            const size_t r0o = (size_t)qr * HD + cb;
            const size_t r8o = (size_t)(qr + 8) * HD + cb;
            qf[0][kc][0] = *(const uint32_t*)(Qh + r0o);
            qf[0][kc][1] = *(const uint32_t*)(Qh + r8o);
            qf[0][kc][2] = *(const uint32_t*)(Qh + r0o + 8);
            qf[0][kc][3] = *(const uint32_t*)(Qh + r8o + 8);
            qf[1][kc][0] = *(const uint32_t*)(Ql + r0o);
            qf[1][kc][1] = *(const uint32_t*)(Ql + r8o);
            qf[1][kc][2] = *(const uint32_t*)(Ql + r0o + 8);
            qf[1][kc][3] = *(const uint32_t*)(Ql + r8o + 8);
        }
    }

    float o[8][4];
#pragma unroll
    for (int nt = 0; nt < 8; nt++)
#pragma unroll
        for (int j = 0; j < 4; j++) o[nt][j] = 0.f;
    float mrow[2] = {-1e30f, -1e30f};
    float lrow[2] = {0.f, 0.f};

    for (int kt = 0; kt < ntiles; kt++) {
        const int k0 = kt * 64;
        CP_WAIT1();
        __syncthreads();
        if (kt + 2 < ntiles) prefetch_kv(kt + 2);
        CP_COMMIT();
        const uint32_t sb = sbase + (kt % 3) * F_STAGE;

        // S = Q K^T
        float s[8][4];
#pragma unroll
        for (int nt = 0; nt < 8; nt++)
#pragma unroll
            for (int j = 0; j < 4; j++) s[nt][j] = 0.f;

        const int brow_base = ((lane >> 4) << 3) + (lane & 7);
#pragma unroll
        for (int kc = 0; kc < 4; kc++) {
            const int bcol = kc * 16 + ((lane >> 3) & 1) * 8;
#pragma unroll
            for (int p = 0; p < 4; p++) {
                const uint32_t kd = sb + ((brow_base + p * 16) * FQ + bcol) * 2;
                uint32_t h0, h1, h2, h3, l0, l1, l2, l3;
                ldsm4(h0, h1, h2, h3, kd);
                ldsm4(l0, l1, l2, l3, kd + F_KBYTES);
                mma16816(s[2 * p],     qf[0][kc], h0, h1);
                mma16816(s[2 * p],     qf[1][kc], h0, h1);
                mma16816(s[2 * p],     qf[0][kc], l0, l1);
                mma16816(s[2 * p + 1], qf[0][kc], h2, h3);
                mma16816(s[2 * p + 1], qf[1][kc], h2, h3);
                mma16816(s[2 * p + 1], qf[0][kc], l2, l3);
            }
        }

        // causal mask on the diagonal band
        if (kt >= 2 * qi) {
#pragma unroll
            for (int nt = 0; nt < 8; nt++)
#pragma unroll
                for (int j = 0; j < 4; j++) {
                    const int gr = q0 + w * 16 + (lane >> 2) + (j >> 1) * 8;
                    const int gc = k0 + nt * 8 + (lane & 3) * 2 + (j & 1);
                    if (gc > gr) s[nt][j] = -1e30f;
                }
        }

        // online softmax
#pragma unroll
        for (int h = 0; h < 2; h++) {
            float mx = -1e30f;
#pragma unroll
            for (int nt = 0; nt < 8; nt++)
                mx = fmaxf(mx, fmaxf(s[nt][2 * h], s[nt][2 * h + 1]));
            mx = fmaxf(mx, __shfl_xor_sync(0xffffffffu, mx, 1));
            mx = fmaxf(mx, __shfl_xor_sync(0xffffffffu, mx, 2));
            const float mnew = fmaxf(mrow[h], mx);
            const float alpha = __expf(mrow[h] - mnew);
            float sum = 0.f;
#pragma unroll
            for (int nt = 0; nt < 8; nt++) {
                float e0 = __expf(s[nt][2 * h]     - mnew);
                float e1 = __expf(s[nt][2 * h + 1] - mnew);
                s[nt][2 * h] = e0; s[nt][2 * h + 1] = e1;
                sum += e0 + e1;
            }
            sum += __shfl_xor_sync(0xffffffffu, sum, 1);
            sum += __shfl_xor_sync(0xffffffffu, sum, 2);
            lrow[h] = lrow[h] * alpha + sum;
            mrow[h] = mnew;
#pragma unroll
            for (int nt = 0; nt < 8; nt++) {
                o[nt][2 * h] *= alpha; o[nt][2 * h + 1] *= alpha;
            }
        }

        // O += P V
        const int vcol_base = (lane >> 4) << 3;
        const int vrow_base = (lane & 7) + ((lane >> 3) & 1) * 8;
#pragma unroll
        for (int kc = 0; kc < 4; kc++) {
            uint32_t ph[4], pl[4];
            {
                const float* c0 = s[2 * kc];
                const float* c1 = s[2 * kc + 1];
                __nv_bfloat162 t0 = __floats2bfloat162_rn(c0[0], c0[1]);
                __nv_bfloat162 t1 = __floats2bfloat162_rn(c0[2], c0[3]);
                __nv_bfloat162 t2 = __floats2bfloat162_rn(c1[0], c1[1]);
                __nv_bfloat162 t3 = __floats2bfloat162_rn(c1[2], c1[3]);
                ph[0] = *(uint32_t*)&t0; ph[1] = *(uint32_t*)&t1;
                ph[2] = *(uint32_t*)&t2; ph[3] = *(uint32_t*)&t3;
                __nv_bfloat162 u0 = __floats2bfloat162_rn(
                    c0[0] - __bfloat162float(t0.x), c0[1] - __bfloat162float(t0.y));
                __nv_bfloat162 u1 = __floats2bfloat162_rn(
                    c0[2] - __bfloat162float(t1.x), c0[3] - __bfloat162float(t1.y));
                __nv_bfloat162 u2 = __floats2bfloat162_rn(
                    c1[0] - __bfloat162float(t2.x), c1[1] - __bfloat162float(t2.y));
                __nv_bfloat162 u3 = __floats2bfloat162_rn(
                    c1[2] - __bfloat162float(t3.x), c1[3] - __bfloat162float(t3.y));
                pl[0] = *(uint32_t*)&u0; pl[1] = *(uint32_t*)&u1;
                pl[2] = *(uint32_t*)&u2; pl[3] = *(uint32_t*)&u3;
            }
            const int vrow = kc * 16 + vrow_base;
#pragma unroll
            for (int p = 0; p < 4; p++) {
                const uint32_t vd =
                    sb + 2 * F_KBYTES + (vrow * FQ + p * 16 + vcol_base) * 2;
                uint32_t h0, h1, h2, h3, l0, l1, l2, l3;
                ldsm4t(h0, h1, h2, h3, vd);
                ldsm4t(l0, l1, l2, l3, vd + F_KBYTES);
                mma16816(o[2 * p],     ph, h0, h1);
                mma16816(o[2 * p],     pl, h0, h1);
                mma16816(o[2 * p],     ph, l0, l1);
                mma16816(o[2 * p + 1], ph, h2, h3);
                mma16816(o[2 * p + 1], pl, h2, h3);
                mma16816(o[2 * p + 1], ph, l2, l3);
            }
        }
    }

    // epilogue
    const int b = bh >> 4;
    const int hh = bh & 15;
    const float inv0 = 1.0f / lrow[0];
    const float inv1 = 1.0f / lrow[1];
    const int t0 = q0 + w * 16 + (lane >> 2);
#pragma unroll
    for (int nt = 0; nt < 8; nt++) {
        const int d = nt * 8 + (lane & 3) * 2;
        {
            float f0 = o[nt][0] * inv0, f1 = o[nt][1] * inv0;
            __nv_bfloat162 hi2 = __floats2bfloat162_rn(f0, f1);
            __nv_bfloat162 lo2 = __floats2bfloat162_rn(
                f0 - __bfloat162float(hi2.x), f1 - __bfloat162float(hi2.y));
            const size_t off = ((size_t)(b * T_SEQ + t0)) * CH + hh * HD + d;
            *(__nv_bfloat162*)&g_at_hi[off] = hi2;
            *(__nv_bfloat162*)&g_at_lo[off] = lo2;
        }
        {
            float f0 = o[nt][2] * inv1, f1 = o[nt][3] * inv1;
            __nv_bfloat162 hi2 = __floats2bfloat162_rn(f0, f1);
            __nv_bfloat162 lo2 = __floats2bfloat162_rn(
                f0 - __bfloat162float(hi2.x), f1 - __bfloat162float(hi2.y));
            const size_t off = ((size_t)(b * T_SEQ + t0 + 8)) * CH + hh * HD + d;
            *(__nv_bfloat162*)&g_at_hi[off] = hi2;
            *(__nv_bfloat162*)&g_at_lo[off] = lo2;
        }
    }
}

// ---------------------------------------------------------------------------
// Launch. Motif conv branch (d_in[3], d_in[4]) is mathematically a no-op:
// its bias is constant along the softmax reduction axis, so softmax cancels it.
// ---------------------------------------------------------------------------
extern "C" void kernel_launch(void* const* d_in, const int* in_sizes, int n_in,
                              void* d_out, int out_size)
{
    (void)in_sizes; (void)n_in; (void)out_size;
    const float* x    = (const float*)d_in[0];
    const float* Wqkv = (const float*)d_in[1];
    const float* bqkv = (const float*)d_in[2];
    const float* Wout = (const float*)d_in[5];
    const float* bout = (const float*)d_in[6];
    float* out = (float*)d_out;

    cudaFuncSetAttribute(gemm_mma,
                         cudaFuncAttributeMaxDynamicSharedMemorySize, GEMM_SMEM);
    cudaFuncSetAttribute(flash_mma,
                         cudaFuncAttributeMaxDynamicSharedMemorySize, FLASH_SMEM);

    bf16 *xh, *xl, *wqh, *wql, *woh, *wol, *ath, *atl;
    cudaGetSymbolAddress((void**)&xh,  g_x_hi);
    cudaGetSymbolAddress((void**)&xl,  g_x_lo);
    cudaGetSymbolAddress((void**)&wqh, g_wq_hi);
    cudaGetSymbolAddress((void**)&wql, g_wq_lo);
    cudaGetSymbolAddress((void**)&woh, g_wo_hi);
    cudaGetSymbolAddress((void**)&wol, g_wo_lo);
    cudaGetSymbolAddress((void**)&ath, g_at_hi);
    cudaGetSymbolAddress((void**)&atl, g_at_lo);

    convert_split<<<BT * CH / 1024, 256>>>(x, xh, xl, BT * CH);
    convert_split<<<3 * CH * CH / 1024, 256>>>(Wqkv, wqh, wql, 3 * CH * CH);
    convert_split<<<CH * CH / 1024, 256>>>(Wout, woh, wol, CH * CH);

    // QKV projection -> g_qkv (bf16 hi/lo, Q pre-scaled)
    gemm_mma<<<dim3(3 * CH / 64, BT / 128), 256, GEMM_SMEM>>>(
        xh, xl, wqh, wql, bqkv, nullptr, 3 * CH, CH, 0);

    // flash causal attention -> g_at (bf16 hi/lo)
    flash_mma<<<dim3(T_SEQ / 128, BHCNT), 256, FLASH_SMEM>>>();

    // output projection -> d_out (fp32)
    gemm_mma<<<dim3(CH / 64, BT / 128), 256, GEMM_SMEM>>>(
        ath, atl, woh, wol, bout, out, CH, CH, 1);
}

// round 12
// speedup vs baseline: 1.0059x; 1.0059x over previous
#include <cuda_runtime.h>
#include <cuda_bf16.h>
#include <cstdint>

#define T_SEQ 2048
#define CH    1024
#define NH    16
#define HD    64
#define BATCH 2
#define BT    (BATCH*T_SEQ)   // 4096
#define BHCNT (BATCH*NH)      // 32

typedef __nv_bfloat16 bf16;

// ---------------- scratch (no cudaMalloc allowed) ----------------
__device__ bf16 g_x_hi[(size_t)BT * CH],    g_x_lo[(size_t)BT * CH];
__device__ bf16 g_wq_hi[(size_t)3*CH*CH],   g_wq_lo[(size_t)3*CH*CH];
__device__ bf16 g_wo_hi[(size_t)CH*CH],     g_wo_lo[(size_t)CH*CH];
__device__ bf16 g_qkv_hi[(size_t)3*BHCNT*T_SEQ*HD], g_qkv_lo[(size_t)3*BHCNT*T_SEQ*HD];
__device__ bf16 g_at_hi[(size_t)BT * CH],   g_at_lo[(size_t)BT * CH];

// ---------------- helpers ----------------
__device__ __forceinline__ uint32_t smem_u32(const void* p) {
    uint32_t a;
    asm("{ .reg .u64 t; cvta.to.shared.u64 t, %1; cvt.u32.u64 %0, t; }"
        : "=r"(a) : "l"(p));
    return a;
}
#define CP_ASYNC16(dst, src) \
    asm volatile("cp.async.cg.shared.global [%0], [%1], 16;" :: "r"(dst), "l"(src))
#define CP_COMMIT() asm volatile("cp.async.commit_group;" ::: "memory")
#define CP_WAIT1()  asm volatile("cp.async.wait_group 1;" ::: "memory")

__device__ __forceinline__ void ldsm4(uint32_t& r0, uint32_t& r1,
                                      uint32_t& r2, uint32_t& r3, uint32_t addr) {
    asm volatile("ldmatrix.sync.aligned.m8n8.x4.shared.b16 {%0,%1,%2,%3}, [%4];"
                 : "=r"(r0), "=r"(r1), "=r"(r2), "=r"(r3) : "r"(addr));
}
__device__ __forceinline__ void ldsm4t(uint32_t& r0, uint32_t& r1,
                                       uint32_t& r2, uint32_t& r3, uint32_t addr) {
    asm volatile("ldmatrix.sync.aligned.m8n8.x4.trans.shared.b16 {%0,%1,%2,%3}, [%4];"
                 : "=r"(r0), "=r"(r1), "=r"(r2), "=r"(r3) : "r"(addr));
}
__device__ __forceinline__ void mma16816(float* c, const uint32_t* a,
                                         uint32_t b0, uint32_t b1) {
    asm volatile("mma.sync.aligned.m16n8k16.row.col.f32.bf16.bf16.f32 "
                 "{%0,%1,%2,%3}, {%4,%5,%6,%7}, {%8,%9}, {%0,%1,%2,%3};"
                 : "+f"(c[0]), "+f"(c[1]), "+f"(c[2]), "+f"(c[3])
                 : "r"(a[0]), "r"(a[1]), "r"(a[2]), "r"(a[3]), "r"(b0), "r"(b1));
}

// ---------------------------------------------------------------------------
// Split fp32 -> bf16 hi + lo residual
// ---------------------------------------------------------------------------
__global__ __launch_bounds__(256) void convert_split(
    const float* __restrict__ src, bf16* __restrict__ hi,
    bf16* __restrict__ lo, int n)
{
    int i = (blockIdx.x * 256 + threadIdx.x) * 4;
    if (i >= n) return;
    float4 v = *(const float4*)(src + i);
    __nv_bfloat162 h01 = __floats2bfloat162_rn(v.x, v.y);
    __nv_bfloat162 h23 = __floats2bfloat162_rn(v.z, v.w);
    __nv_bfloat162 l01 = __floats2bfloat162_rn(v.x - __bfloat162float(h01.x),
                                               v.y - __bfloat162float(h01.y));
    __nv_bfloat162 l23 = __floats2bfloat162_rn(v.z - __bfloat162float(h23.x),
                                               v.w - __bfloat162float(h23.y));
    *(__nv_bfloat162*)(hi + i)     = h01;
    *(__nv_bfloat162*)(hi + i + 2) = h23;
    *(__nv_bfloat162*)(lo + i)     = l01;
    *(__nv_bfloat162*)(lo + i + 2) = l23;
}

// ---------------------------------------------------------------------------
// bf16x3 GEMM via mma.sync (NT): CTA 128x128, warp tile 32x64 (8 warps),
// BK=32, 3-stage cp.async, XOR swizzle, 2 CTAs/SM.
// B-fragments phased (hi then lo) to keep regs under the 128 cap.
// mode 0: write bf16 hi/lo into g_qkv (Q pre-scaled by 0.125)
// mode 1: write fp32 row-major into Cout
// ---------------------------------------------------------------------------
#define GAB 8192                         // per array: 128 rows x 64B
#define G_STAGE (4 * GAB)                // Ahi,Alo,Bhi,Blo = 32768
#define GEMM_SMEM (3 * G_STAGE)          // 98304

__device__ __forceinline__ uint32_t gswz(int r, int c16) {
    return (uint32_t)(r * 64 + ((c16 ^ ((r >> 1) & 3)) << 4));
}

__global__ __launch_bounds__(256, 2) void gemm_mma(
    const bf16* __restrict__ Ahi, const bf16* __restrict__ Alo,
    const bf16* __restrict__ Bhi, const bf16* __restrict__ Blo,
    const float* __restrict__ bias, float* __restrict__ Cout,
    int N, int K, int mode)
{
    extern __shared__ __align__(16) bf16 sm[];
    const uint32_t sbase = smem_u32(sm);

    const int tid = threadIdx.x;
    const int lane = tid & 31;
    const int w = tid >> 5;
    const int wm = w & 3;          // M group of 32
    const int wn = w >> 2;         // N group of 64
    const int m0 = blockIdx.y * 128;
    const int n0 = blockIdx.x * 128;

    const int lr  = tid >> 1;            // 0..127
    const int lc0 = (tid & 1) * 2;       // c16 base 0 or 2

    auto prefetch = [&](int c) {
        const uint32_t sb = sbase + (c % 3) * G_STAGE;
        const int k0 = c * 32;
#pragma unroll
        for (int j = 0; j < 2; j++) {
            const int c16 = lc0 + j;
            const uint32_t sw = gswz(lr, c16);
            const size_t ga = (size_t)(m0 + lr) * K + k0 + c16 * 8;
            const size_t gb = (size_t)(n0 + lr) * K + k0 + c16 * 8;
            CP_ASYNC16(sb + sw,           Ahi + ga);
            CP_ASYNC16(sb + sw + GAB,     Alo + ga);
            CP_ASYNC16(sb + sw + 2 * GAB, Bhi + gb);
            CP_ASYNC16(sb + sw + 3 * GAB, Blo + gb);
        }
    };

    float acc[2][8][4];
#pragma unroll
    for (int mi = 0; mi < 2; mi++)
#pragma unroll
        for (int nt = 0; nt < 8; nt++)
#pragma unroll
            for (int j = 0; j < 4; j++) acc[mi][nt][j] = 0.f;

    prefetch(0); CP_COMMIT();
    prefetch(1); CP_COMMIT();

    const int NC = K / 32;
    for (int c = 0; c < NC; c++) {
        CP_WAIT1();
        __syncthreads();
        if (c + 2 < NC) prefetch(c + 2);
        CP_COMMIT();
        const uint32_t sb = sbase + (c % 3) * G_STAGE;

#pragma unroll
        for (int kc = 0; kc < 2; kc++) {
            const int kk16 = kc * 2;
            // A fragments (hi + lo)
            uint32_t af[2][2][4];
            const int arow = wm * 32 + (lane & 15);
            const int ac16 = kk16 + (lane >> 4);
#pragma unroll
            for (int mi = 0; mi < 2; mi++) {
                const uint32_t ad = sb + gswz(arow + mi * 16, ac16);
                ldsm4(af[0][mi][0], af[0][mi][1], af[0][mi][2], af[0][mi][3], ad);
                ldsm4(af[1][mi][0], af[1][mi][1], af[1][mi][2], af[1][mi][3],
                      ad + GAB);
            }
            const int brow_base = wn * 64 + ((lane >> 4) << 3) + (lane & 7);
            const int bc16 = kk16 + ((lane >> 3) & 1);
            // Phase 1: B-hi fragments -> hi*hi and lo*hi terms
            {
                uint32_t bfh[8][2];
#pragma unroll
                for (int p = 0; p < 4; p++) {
                    const uint32_t bd =
                        sb + 2 * GAB + gswz(brow_base + p * 16, bc16);
                    uint32_t r0, r1, r2, r3;
                    ldsm4(r0, r1, r2, r3, bd);
                    bfh[2 * p][0] = r0; bfh[2 * p][1] = r1;
                    bfh[2 * p + 1][0] = r2; bfh[2 * p + 1][1] = r3;
                }
#pragma unroll
                for (int mi = 0; mi < 2; mi++)
#pragma unroll
                    for (int nt = 0; nt < 8; nt++) {
                        mma16816(acc[mi][nt], af[0][mi], bfh[nt][0], bfh[nt][1]);
                        mma16816(acc[mi][nt], af[1][mi], bfh[nt][0], bfh[nt][1]);
                    }
            }
            // Phase 2: B-lo fragments -> hi*lo term
            {
                uint32_t bfl[8][2];
#pragma unroll
                for (int p = 0; p < 4; p++) {
                    const uint32_t bd =
                        sb + 3 * GAB + gswz(brow_base + p * 16, bc16);
                    uint32_t r0, r1, r2, r3;
                    ldsm4(r0, r1, r2, r3, bd);
                    bfl[2 * p][0] = r0; bfl[2 * p][1] = r1;
                    bfl[2 * p + 1][0] = r2; bfl[2 * p + 1][1] = r3;
                }
#pragma unroll
                for (int mi = 0; mi < 2; mi++)
#pragma unroll
                    for (int nt = 0; nt < 8; nt++)
                        mma16816(acc[mi][nt], af[0][mi], bfl[nt][0], bfl[nt][1]);
            }
        }
    }

    // epilogue
#pragma unroll
    for (int mi = 0; mi < 2; mi++) {
        const int rbase = m0 + wm * 32 + mi * 16 + (lane >> 2);
#pragma unroll
        for (int hr = 0; hr < 2; hr++) {
            const int r = rbase + hr * 8;
#pragma unroll
            for (int nt = 0; nt < 8; nt++) {
                const int n = n0 + wn * 64 + nt * 8 + (lane & 3) * 2;
                float2 bb = *(const float2*)&bias[n];
                float f0 = acc[mi][nt][hr * 2 + 0] + bb.x;
                float f1 = acc[mi][nt][hr * 2 + 1] + bb.y;
                if (mode == 0) {
                    const int s = n >> 10;
                    if (s == 0) { f0 *= 0.125f; f1 *= 0.125f; }  // fold 1/sqrt(64) into Q
                    const int b = r >> 11, t = r & 2047;
                    const int hh = (n >> 6) & 15, d = n & 63;
                    __nv_bfloat162 hi2 = __floats2bfloat162_rn(f0, f1);
                    __nv_bfloat162 lo2 = __floats2bfloat162_rn(
                        f0 - __bfloat162float(hi2.x), f1 - __bfloat162float(hi2.y));
                    const size_t o =
                        ((size_t)(s * BHCNT + b * NH + hh) * T_SEQ + t) * HD + d;
                    *(__nv_bfloat162*)&g_qkv_hi[o] = hi2;
                    *(__nv_bfloat162*)&g_qkv_lo[o] = lo2;
                } else {
                    float2 o2 = {f0, f1};
                    *(float2*)&Cout[(size_t)r * N + n] = o2;
                }
            }
        }
    }
}

// ---------------------------------------------------------------------------
// Flash causal attention, bf16x3, 3-stage cp.async K/V pipeline (R8 exact).
// BQ=128, BK=64, 8 warps; warp w owns rows [w*16, w*16+16).
// CTAs remapped heavy-first.
// ---------------------------------------------------------------------------
#define FQ 72
#define F_KBYTES (64 * FQ * 2)              // 9216 bytes per K/V array
#define F_STAGE  (4 * F_KBYTES)             // 36864 bytes per stage
#define F_QOFF   (3 * F_STAGE)              // 110592 byte offset of Q region
#define F_QBYTES (128 * FQ * 2)             // 18432 per Q array
#define FLASH_SMEM (F_QOFF + 2 * F_QBYTES)  // 147456

__global__ __launch_bounds__(256, 1) void flash_mma()
{
    extern __shared__ __align__(16) bf16 smf[];
    const uint32_t sbase = smem_u32(smf);
    bf16* sQh = smf + F_QOFF / 2;
    bf16* sQl = smf + (F_QOFF + F_QBYTES) / 2;

    const int tid = threadIdx.x;
    const int lane = tid & 31;
    const int w = tid >> 5;
    const int qi = (int)gridDim.x - 1 - (int)blockIdx.x;   // heavy tiles first
    const int q0 = qi * 128;
    const int bh = blockIdx.y;

    const bf16* Qh = g_qkv_hi + (size_t)(0 * BHCNT + bh) * T_SEQ * HD;
    const bf16* Ql = g_qkv_lo + (size_t)(0 * BHCNT + bh) * T_SEQ * HD;
    const bf16* Kh = g_qkv_hi + (size_t)(1 * BHCNT + bh) * T_SEQ * HD;
    const bf16* Kl = g_qkv_lo + (size_t)(1 * BHCNT + bh) * T_SEQ * HD;
    const bf16* Vh = g_qkv_hi + (size_t)(2 * BHCNT + bh) * T_SEQ * HD;
    const bf16* Vl = g_qkv_lo + (size_t)(2 * BHCNT + bh) * T_SEQ * HD;

    const int ldr = tid >> 3;
    const int ldc = (tid & 7) * 8;

    auto prefetch_kv = [&](int kt) {
        const uint32_t sb = sbase + (kt % 3) * F_STAGE;
        const int k0 = kt * 64;
#pragma unroll
        for (int it = 0; it < 2; it++) {
            const int r = it * 32 + ldr;
            const uint32_t d = sb + (r * FQ + ldc) * 2;
            const size_t g = (size_t)(k0 + r) * HD + ldc;
            CP_ASYNC16(d,                Kh + g);
            CP_ASYNC16(d + F_KBYTES,     Kl + g);
            CP_ASYNC16(d + 2 * F_KBYTES, Vh + g);
            CP_ASYNC16(d + 3 * F_KBYTES, Vl + g);
        }
    };

    const int ntiles = 2 * qi + 2;
    prefetch_kv(0); CP_COMMIT();
    prefetch_kv(1); CP_COMMIT();

    // stage Q, build per-warp Q fragments (hi + lo resident)
#pragma unroll
    for (int it = 0; it < 4; it++) {
        const int r = it * 32 + ldr;
        const size_t g = (size_t)(q0 + r) * HD + ldc;
        *(uint4*)&sQh[r * FQ + ldc] = *(const uint4*)(Qh + g);
        *(uint4*)&sQl[r * FQ + ldc] = *(const uint4*)(Ql + g);
    }
    __syncthreads();
    uint32_t qf[2][4][4];
    {
        const int qrow = w * 16 + (lane & 15);
#pragma unroll
        for (int kc = 0; kc < 4; kc++) {
            const int col = kc * 16 + 8 * (lane >> 4);
            ldsm4(qf[0][kc][0], qf[0][kc][1], qf[0][kc][2], qf[0][kc][3],
                  smem_u32(&sQh[qrow * FQ + col]));
            ldsm4(qf[1][kc][0], qf[1][kc][1], qf[1][kc][2], qf[1][kc][3],
                  smem_u32(&sQl[qrow * FQ + col]));
        }
    }

    float o[8][4];
#pragma unroll
    for (int nt = 0; nt < 8; nt++)
#pragma unroll
        for (int j = 0; j < 4; j++) o[nt][j] = 0.f;
    float mrow[2] = {-1e30f, -1e30f};
    float lrow[2] = {0.f, 0.f};

    for (int kt = 0; kt < ntiles; kt++) {
        const int k0 = kt * 64;
        CP_WAIT1();
        __syncthreads();
        if (kt + 2 < ntiles) prefetch_kv(kt + 2);
        CP_COMMIT();
        const uint32_t sb = sbase + (kt % 3) * F_STAGE;

        // S = Q K^T
        float s[8][4];
#pragma unroll
        for (int nt = 0; nt < 8; nt++)
#pragma unroll
            for (int j = 0; j < 4; j++) s[nt][j] = 0.f;

        const int brow_base = ((lane >> 4) << 3) + (lane & 7);
#pragma unroll
        for (int kc = 0; kc < 4; kc++) {
            const int bcol = kc * 16 + ((lane >> 3) & 1) * 8;
#pragma unroll
            for (int p = 0; p < 4; p++) {
                const uint32_t kd = sb + ((brow_base + p * 16) * FQ + bcol) * 2;
                uint32_t h0, h1, h2, h3, l0, l1, l2, l3;
                ldsm4(h0, h1, h2, h3, kd);
                ldsm4(l0, l1, l2, l3, kd + F_KBYTES);
                mma16816(s[2 * p],     qf[0][kc], h0, h1);
                mma16816(s[2 * p],     qf[1][kc], h0, h1);
                mma16816(s[2 * p],     qf[0][kc], l0, l1);
                mma16816(s[2 * p + 1], qf[0][kc], h2, h3);
                mma16816(s[2 * p + 1], qf[1][kc], h2, h3);
                mma16816(s[2 * p + 1], qf[0][kc], l2, l3);
            }
        }

        // causal mask on the diagonal band
        if (kt >= 2 * qi) {
#pragma unroll
            for (int nt = 0; nt < 8; nt++)
#pragma unroll
                for (int j = 0; j < 4; j++) {
                    const int gr = q0 + w * 16 + (lane >> 2) + (j >> 1) * 8;
                    const int gc = k0 + nt * 8 + (lane & 3) * 2 + (j & 1);
                    if (gc > gr) s[nt][j] = -1e30f;
                }
        }

        // online softmax
#pragma unroll
        for (int h = 0; h < 2; h++) {
            float mx = -1e30f;
#pragma unroll
            for (int nt = 0; nt < 8; nt++)
                mx = fmaxf(mx, fmaxf(s[nt][2 * h], s[nt][2 * h + 1]));
            mx = fmaxf(mx, __shfl_xor_sync(0xffffffffu, mx, 1));
            mx = fmaxf(mx, __shfl_xor_sync(0xffffffffu, mx, 2));
            const float mnew = fmaxf(mrow[h], mx);
            const float alpha = __expf(mrow[h] - mnew);
            float sum = 0.f;
#pragma unroll
            for (int nt = 0; nt < 8; nt++) {
                float e0 = __expf(s[nt][2 * h]     - mnew);
                float e1 = __expf(s[nt][2 * h + 1] - mnew);
                s[nt][2 * h] = e0; s[nt][2 * h + 1] = e1;
                sum += e0 + e1;
            }
            sum += __shfl_xor_sync(0xffffffffu, sum, 1);
            sum += __shfl_xor_sync(0xffffffffu, sum, 2);
            lrow[h] = lrow[h] * alpha + sum;
            mrow[h] = mnew;
#pragma unroll
            for (int nt = 0; nt < 8; nt++) {
                o[nt][2 * h] *= alpha; o[nt][2 * h + 1] *= alpha;
            }
        }

        // O += P V
        const int vcol_base = (lane >> 4) << 3;
        const int vrow_base = (lane & 7) + ((lane >> 3) & 1) * 8;
#pragma unroll
        for (int kc = 0; kc < 4; kc++) {
            uint32_t ph[4], pl[4];
            {
                const float* c0 = s[2 * kc];
                const float* c1 = s[2 * kc + 1];
                __nv_bfloat162 t0 = __floats2bfloat162_rn(c0[0], c0[1]);
                __nv_bfloat162 t1 = __floats2bfloat162_rn(c0[2], c0[3]);
                __nv_bfloat162 t2 = __floats2bfloat162_rn(c1[0], c1[1]);
                __nv_bfloat162 t3 = __floats2bfloat162_rn(c1[2], c1[3]);
                ph[0] = *(uint32_t*)&t0; ph[1] = *(uint32_t*)&t1;
                ph[2] = *(uint32_t*)&t2; ph[3] = *(uint32_t*)&t3;
                __nv_bfloat162 u0 = __floats2bfloat162_rn(
                    c0[0] - __bfloat162float(t0.x), c0[1] - __bfloat162float(t0.y));
                __nv_bfloat162 u1 = __floats2bfloat162_rn(
                    c0[2] - __bfloat162float(t1.x), c0[3] - __bfloat162float(t1.y));
                __nv_bfloat162 u2 = __floats2bfloat162_rn(
                    c1[0] - __bfloat162float(t2.x), c1[1] - __bfloat162float(t2.y));
                __nv_bfloat162 u3 = __floats2bfloat162_rn(
                    c1[2] - __bfloat162float(t3.x), c1[3] - __bfloat162float(t3.y));
                pl[0] = *(uint32_t*)&u0; pl[1] = *(uint32_t*)&u1;
                pl[2] = *(uint32_t*)&u2; pl[3] = *(uint32_t*)&u3;
            }
            const int vrow = kc * 16 + vrow_base;
#pragma unroll
            for (int p = 0; p < 4; p++) {
                const uint32_t vd =
                    sb + 2 * F_KBYTES + (vrow * FQ + p * 16 + vcol_base) * 2;
                uint32_t h0, h1, h2, h3, l0, l1, l2, l3;
                ldsm4t(h0, h1, h2, h3, vd);
                ldsm4t(l0, l1, l2, l3, vd + F_KBYTES);
                mma16816(o[2 * p],     ph, h0, h1);
                mma16816(o[2 * p],     pl, h0, h1);
                mma16816(o[2 * p],     ph, l0, l1);
                mma16816(o[2 * p + 1], ph, h2, h3);
                mma16816(o[2 * p + 1], pl, h2, h3);
                mma16816(o[2 * p + 1], ph, l2, l3);
            }
        }
    }

    // epilogue
    const int b = bh >> 4;
    const int hh = bh & 15;
    const float inv0 = 1.0f / lrow[0];
    const float inv1 = 1.0f / lrow[1];
    const int t0 = q0 + w * 16 + (lane >> 2);
#pragma unroll
    for (int nt = 0; nt < 8; nt++) {
        const int d = nt * 8 + (lane & 3) * 2;
        {
            float f0 = o[nt][0] * inv0, f1 = o[nt][1] * inv0;
            __nv_bfloat162 hi2 = __floats2bfloat162_rn(f0, f1);
            __nv_bfloat162 lo2 = __floats2bfloat162_rn(
                f0 - __bfloat162float(hi2.x), f1 - __bfloat162float(hi2.y));
            const size_t off = ((size_t)(b * T_SEQ + t0)) * CH + hh * HD + d;
            *(__nv_bfloat162*)&g_at_hi[off] = hi2;
            *(__nv_bfloat162*)&g_at_lo[off] = lo2;
        }
        {
            float f0 = o[nt][2] * inv1, f1 = o[nt][3] * inv1;
            __nv_bfloat162 hi2 = __floats2bfloat162_rn(f0, f1);
            __nv_bfloat162 lo2 = __floats2bfloat162_rn(
                f0 - __bfloat162float(hi2.x), f1 - __bfloat162float(hi2.y));
            const size_t off = ((size_t)(b * T_SEQ + t0 + 8)) * CH + hh * HD + d;
            *(__nv_bfloat162*)&g_at_hi[off] = hi2;
            *(__nv_bfloat162*)&g_at_lo[off] = lo2;
        }
    }
}

// ---------------------------------------------------------------------------
// Launch. Motif conv branch (d_in[3], d_in[4]) is mathematically a no-op:
// its bias is constant along the softmax reduction axis, so softmax cancels it.
// ---------------------------------------------------------------------------
extern "C" void kernel_launch(void* const* d_in, const int* in_sizes, int n_in,
                              void* d_out, int out_size)
{
    (void)in_sizes; (void)n_in; (void)out_size;
    const float* x    = (const float*)d_in[0];
    const float* Wqkv = (const float*)d_in[1];
    const float* bqkv = (const float*)d_in[2];
    const float* Wout = (const float*)d_in[5];
    const float* bout = (const float*)d_in[6];
    float* out = (float*)d_out;

    cudaFuncSetAttribute(gemm_mma,
                         cudaFuncAttributeMaxDynamicSharedMemorySize, GEMM_SMEM);
    cudaFuncSetAttribute(flash_mma,
                         cudaFuncAttributeMaxDynamicSharedMemorySize, FLASH_SMEM);

    bf16 *xh, *xl, *wqh, *wql, *woh, *wol, *ath, *atl;
    cudaGetSymbolAddress((void**)&xh,  g_x_hi);
    cudaGetSymbolAddress((void**)&xl,  g_x_lo);
    cudaGetSymbolAddress((void**)&wqh, g_wq_hi);
    cudaGetSymbolAddress((void**)&wql, g_wq_lo);
    cudaGetSymbolAddress((void**)&woh, g_wo_hi);
    cudaGetSymbolAddress((void**)&wol, g_wo_lo);
    cudaGetSymbolAddress((void**)&ath, g_at_hi);
    cudaGetSymbolAddress((void**)&atl, g_at_lo);

    convert_split<<<BT * CH / 1024, 256>>>(x, xh, xl, BT * CH);
    convert_split<<<3 * CH * CH / 1024, 256>>>(Wqkv, wqh, wql, 3 * CH * CH);
    convert_split<<<CH * CH / 1024, 256>>>(Wout, woh, wol, CH * CH);

    // QKV projection -> g_qkv (bf16 hi/lo, Q pre-scaled)
    gemm_mma<<<dim3(3 * CH / 128, BT / 128), 256, GEMM_SMEM>>>(
        xh, xl, wqh, wql, bqkv, nullptr, 3 * CH, CH, 0);

    // flash causal attention -> g_at (bf16 hi/lo)
    flash_mma<<<dim3(T_SEQ / 128, BHCNT), 256, FLASH_SMEM>>>();

    // output projection -> d_out (fp32)
    gemm_mma<<<dim3(CH / 128, BT / 128), 256, GEMM_SMEM>>>(
        ath, atl, woh, wol, bout, out, CH, CH, 1);
}

// round 13
// speedup vs baseline: 1.0508x; 1.0447x over previous
#include <cuda_runtime.h>
#include <cuda_bf16.h>
#include <cstdint>

#define T_SEQ 2048
#define CH    1024
#define NH    16
#define HD    64
#define BATCH 2
#define BT    (BATCH*T_SEQ)   // 4096
#define BHCNT (BATCH*NH)      // 32

typedef __nv_bfloat16 bf16;

// ---------------- scratch (no cudaMalloc allowed) ----------------
__device__ bf16 g_x_hi[(size_t)BT * CH],    g_x_lo[(size_t)BT * CH];
__device__ bf16 g_wq_hi[(size_t)3*CH*CH],   g_wq_lo[(size_t)3*CH*CH];
__device__ bf16 g_wo_hi[(size_t)CH*CH],     g_wo_lo[(size_t)CH*CH];
__device__ bf16 g_qkv_hi[(size_t)3*BHCNT*T_SEQ*HD], g_qkv_lo[(size_t)3*BHCNT*T_SEQ*HD];
__device__ bf16 g_at_hi[(size_t)BT * CH],   g_at_lo[(size_t)BT * CH];

// ---------------- helpers ----------------
__device__ __forceinline__ uint32_t smem_u32(const void* p) {
    uint32_t a;
    asm("{ .reg .u64 t; cvta.to.shared.u64 t, %1; cvt.u32.u64 %0, t; }"
        : "=r"(a) : "l"(p));
    return a;
}
__device__ __forceinline__ float ex2f(float x) {
    float y;
    asm("ex2.approx.f32 %0, %1;" : "=f"(y) : "f"(x));
    return y;
}
#define CP_ASYNC16(dst, src) \
    asm volatile("cp.async.cg.shared.global [%0], [%1], 16;" :: "r"(dst), "l"(src))
#define CP_COMMIT() asm volatile("cp.async.commit_group;" ::: "memory")
#define CP_WAIT1()  asm volatile("cp.async.wait_group 1;" ::: "memory")

__device__ __forceinline__ void ldsm4(uint32_t& r0, uint32_t& r1,
                                      uint32_t& r2, uint32_t& r3, uint32_t addr) {
    asm volatile("ldmatrix.sync.aligned.m8n8.x4.shared.b16 {%0,%1,%2,%3}, [%4];"
                 : "=r"(r0), "=r"(r1), "=r"(r2), "=r"(r3) : "r"(addr));
}
__device__ __forceinline__ void ldsm4t(uint32_t& r0, uint32_t& r1,
                                       uint32_t& r2, uint32_t& r3, uint32_t addr) {
    asm volatile("ldmatrix.sync.aligned.m8n8.x4.trans.shared.b16 {%0,%1,%2,%3}, [%4];"
                 : "=r"(r0), "=r"(r1), "=r"(r2), "=r"(r3) : "r"(addr));
}
__device__ __forceinline__ void mma16816(float* c, const uint32_t* a,
                                         uint32_t b0, uint32_t b1) {
    asm volatile("mma.sync.aligned.m16n8k16.row.col.f32.bf16.bf16.f32 "
                 "{%0,%1,%2,%3}, {%4,%5,%6,%7}, {%8,%9}, {%0,%1,%2,%3};"
                 : "+f"(c[0]), "+f"(c[1]), "+f"(c[2]), "+f"(c[3])
                 : "r"(a[0]), "r"(a[1]), "r"(a[2]), "r"(a[3]), "r"(b0), "r"(b1));
}

// Q prescale: (1/sqrt(64)) * log2(e) so softmax uses raw ex2
#define QSCALE 0.18033688011112042f

// ---------------------------------------------------------------------------
// Split fp32 -> bf16 hi + lo residual
// ---------------------------------------------------------------------------
__global__ __launch_bounds__(256) void convert_split(
    const float* __restrict__ src, bf16* __restrict__ hi,
    bf16* __restrict__ lo, int n)
{
    int i = (blockIdx.x * 256 + threadIdx.x) * 4;
    if (i >= n) return;
    float4 v = *(const float4*)(src + i);
    __nv_bfloat162 h01 = __floats2bfloat162_rn(v.x, v.y);
    __nv_bfloat162 h23 = __floats2bfloat162_rn(v.z, v.w);
    __nv_bfloat162 l01 = __floats2bfloat162_rn(v.x - __bfloat162float(h01.x),
                                               v.y - __bfloat162float(h01.y));
    __nv_bfloat162 l23 = __floats2bfloat162_rn(v.z - __bfloat162float(h23.x),
                                               v.w - __bfloat162float(h23.y));
    *(__nv_bfloat162*)(hi + i)     = h01;
    *(__nv_bfloat162*)(hi + i + 2) = h23;
    *(__nv_bfloat162*)(lo + i)     = l01;
    *(__nv_bfloat162*)(lo + i + 2) = l23;
}

// ---------------------------------------------------------------------------
// bf16x3 GEMM via mma.sync (NT), 2-stage cp.async BK=64, 2 CTAs/SM (R6 exact).
// CTA 128x64, 8 warps (4M x 2N), warp tile 32x32.
// mode 0: write bf16 hi/lo into g_qkv (Q pre-scaled by QSCALE)
// mode 1: write fp32 row-major into Cout
// ---------------------------------------------------------------------------
#define GP 72                               // padded row pitch in bf16 (144B)
#define GA_BYTES (128 * GP * 2)             // 18432
#define GB_BYTES (64 * GP * 2)              // 9216
#define G_STAGE  (2 * GA_BYTES + 2 * GB_BYTES)  // 55296
#define GEMM_SMEM (2 * G_STAGE)             // 110592

__global__ __launch_bounds__(256, 2) void gemm_mma(
    const bf16* __restrict__ Ahi, const bf16* __restrict__ Alo,
    const bf16* __restrict__ Bhi, const bf16* __restrict__ Blo,
    const float* __restrict__ bias, float* __restrict__ Cout,
    int N, int K, int mode)
{
    extern __shared__ __align__(16) bf16 sm[];
    const uint32_t sbase = smem_u32(sm);

    const int tid = threadIdx.x;
    const int lane = tid & 31;
    const int w = tid >> 5;
    const int wm = w & 3;          // 0..3 -> M group of 32
    const int wn = w >> 2;         // 0..1 -> N group of 32
    const int m0 = blockIdx.y * 128;
    const int n0 = blockIdx.x * 64;

    const int ldr = tid >> 3;          // 0..31
    const int ldc = (tid & 7) * 8;     // 0..56

    auto prefetch = [&](int c) {
        const uint32_t sb = sbase + (c & 1) * G_STAGE;
        const int k0 = c * 64;
#pragma unroll
        for (int it = 0; it < 4; it++) {
            const int r = it * 32 + ldr;
            const uint32_t d = sb + (r * GP + ldc) * 2;
            const size_t ga = (size_t)(m0 + r) * K + k0 + ldc;
            CP_ASYNC16(d,            Ahi + ga);
            CP_ASYNC16(d + GA_BYTES, Alo + ga);
        }
#pragma unroll
        for (int it = 0; it < 2; it++) {
            const int r = it * 32 + ldr;
            const uint32_t d = sb + 2 * GA_BYTES + (r * GP + ldc) * 2;
            const size_t gb = (size_t)(n0 + r) * K + k0 + ldc;
            CP_ASYNC16(d,            Bhi + gb);
            CP_ASYNC16(d + GB_BYTES, Blo + gb);
        }
    };

    float acc[2][4][4];
#pragma unroll
    for (int mi = 0; mi < 2; mi++)
#pragma unroll
        for (int nt = 0; nt < 4; nt++)
#pragma unroll
            for (int j = 0; j < 4; j++) acc[mi][nt][j] = 0.f;

    prefetch(0); CP_COMMIT();
    prefetch(1); CP_COMMIT();

    const int NC = K / 64;
    for (int c = 0; c < NC; c++) {
        CP_WAIT1();
        __syncthreads();
        const uint32_t sb = sbase + (c & 1) * G_STAGE;

#pragma unroll
        for (int kc = 0; kc < 4; kc++) {
            const int kk = kc * 16;
            uint32_t af[2][2][4];
            const int arow = wm * 32 + (lane & 15);
            const int acol = kk + 8 * (lane >> 4);
#pragma unroll
            for (int mi = 0; mi < 2; mi++) {
                const uint32_t ad = sb + ((arow + mi * 16) * GP + acol) * 2;
                ldsm4(af[0][mi][0], af[0][mi][1], af[0][mi][2], af[0][mi][3], ad);
                ldsm4(af[1][mi][0], af[1][mi][1], af[1][mi][2], af[1][mi][3],
                      ad + GA_BYTES);
            }
            uint32_t bfh[4][2], bfl[4][2];
            const int brow_base = wn * 32 + ((lane >> 4) << 3) + (lane & 7);
            const int bcol = kk + ((lane >> 3) & 1) * 8;
#pragma unroll
            for (int p = 0; p < 2; p++) {
                const uint32_t bd =
                    sb + 2 * GA_BYTES + ((brow_base + p * 16) * GP + bcol) * 2;
                uint32_t r0, r1, r2, r3;
                ldsm4(r0, r1, r2, r3, bd);
                bfh[2 * p][0] = r0; bfh[2 * p][1] = r1;
                bfh[2 * p + 1][0] = r2; bfh[2 * p + 1][1] = r3;
                ldsm4(r0, r1, r2, r3, bd + GB_BYTES);
                bfl[2 * p][0] = r0; bfl[2 * p][1] = r1;
                bfl[2 * p + 1][0] = r2; bfl[2 * p + 1][1] = r3;
            }
#pragma unroll
            for (int mi = 0; mi < 2; mi++)
#pragma unroll
                for (int nt = 0; nt < 4; nt++) {
                    mma16816(acc[mi][nt], af[0][mi], bfh[nt][0], bfh[nt][1]);
                    mma16816(acc[mi][nt], af[1][mi], bfh[nt][0], bfh[nt][1]);
                    mma16816(acc[mi][nt], af[0][mi], bfl[nt][0], bfl[nt][1]);
                }
        }
        __syncthreads();
        if (c + 2 < NC) prefetch(c + 2);
        CP_COMMIT();
    }

    // epilogue
#pragma unroll
    for (int mi = 0; mi < 2; mi++) {
        const int rbase = m0 + wm * 32 + mi * 16 + (lane >> 2);
#pragma unroll
        for (int hr = 0; hr < 2; hr++) {
            const int r = rbase + hr * 8;
#pragma unroll
            for (int nt = 0; nt < 4; nt++) {
                const int n = n0 + wn * 32 + nt * 8 + (lane & 3) * 2;
                float2 bb = *(const float2*)&bias[n];
                float f0 = acc[mi][nt][hr * 2 + 0] + bb.x;
                float f1 = acc[mi][nt][hr * 2 + 1] + bb.y;
                if (mode == 0) {
                    const int s = n >> 10;
                    if (s == 0) { f0 *= QSCALE; f1 *= QSCALE; }  // 1/sqrt(64)*log2e into Q
                    const int b = r >> 11, t = r & 2047;
                    const int hh = (n >> 6) & 15, d = n & 63;
                    __nv_bfloat162 hi2 = __floats2bfloat162_rn(f0, f1);
                    __nv_bfloat162 lo2 = __floats2bfloat162_rn(
                        f0 - __bfloat162float(hi2.x), f1 - __bfloat162float(hi2.y));
                    const size_t o =
                        ((size_t)(s * BHCNT + b * NH + hh) * T_SEQ + t) * HD + d;
                    *(__nv_bfloat162*)&g_qkv_hi[o] = hi2;
                    *(__nv_bfloat162*)&g_qkv_lo[o] = lo2;
                } else {
                    float2 o2 = {f0, f1};
                    *(float2*)&Cout[(size_t)r * N + n] = o2;
                }
            }
        }
    }
}

// ---------------------------------------------------------------------------
// Flash causal attention, bf16x3, 3-stage cp.async K/V pipeline (R8 exact,
// with ex2-domain softmax). BQ=128, BK=64, 8 warps; warp w owns 16 rows.
// CTAs remapped heavy-first.
// ---------------------------------------------------------------------------
#define FQ 72
#define F_KBYTES (64 * FQ * 2)              // 9216 bytes per K/V array
#define F_STAGE  (4 * F_KBYTES)             // 36864 bytes per stage
#define F_QOFF   (3 * F_STAGE)              // 110592 byte offset of Q region
#define F_QBYTES (128 * FQ * 2)             // 18432 per Q array
#define FLASH_SMEM (F_QOFF + 2 * F_QBYTES)  // 147456

__global__ __launch_bounds__(256, 1) void flash_mma()
{
    extern __shared__ __align__(16) bf16 smf[];
    const uint32_t sbase = smem_u32(smf);
    bf16* sQh = smf + F_QOFF / 2;
    bf16* sQl = smf + (F_QOFF + F_QBYTES) / 2;

    const int tid = threadIdx.x;
    const int lane = tid & 31;
    const int w = tid >> 5;
    const int qi = (int)gridDim.x - 1 - (int)blockIdx.x;   // heavy tiles first
    const int q0 = qi * 128;
    const int bh = blockIdx.y;

    const bf16* Qh = g_qkv_hi + (size_t)(0 * BHCNT + bh) * T_SEQ * HD;
    const bf16* Ql = g_qkv_lo + (size_t)(0 * BHCNT + bh) * T_SEQ * HD;
    const bf16* Kh = g_qkv_hi + (size_t)(1 * BHCNT + bh) * T_SEQ * HD;
    const bf16* Kl = g_qkv_lo + (size_t)(1 * BHCNT + bh) * T_SEQ * HD;
    const bf16* Vh = g_qkv_hi + (size_t)(2 * BHCNT + bh) * T_SEQ * HD;
    const bf16* Vl = g_qkv_lo + (size_t)(2 * BHCNT + bh) * T_SEQ * HD;

    const int ldr = tid >> 3;
    const int ldc = (tid & 7) * 8;

    auto prefetch_kv = [&](int kt) {
        const uint32_t sb = sbase + (kt % 3) * F_STAGE;
        const int k0 = kt * 64;
#pragma unroll
        for (int it = 0; it < 2; it++) {
            const int r = it * 32 + ldr;
            const uint32_t d = sb + (r * FQ + ldc) * 2;
            const size_t g = (size_t)(k0 + r) * HD + ldc;
            CP_ASYNC16(d,                Kh + g);
            CP_ASYNC16(d + F_KBYTES,     Kl + g);
            CP_ASYNC16(d + 2 * F_KBYTES, Vh + g);
            CP_ASYNC16(d + 3 * F_KBYTES, Vl + g);
        }
    };

    const int ntiles = 2 * qi + 2;
    prefetch_kv(0); CP_COMMIT();
    prefetch_kv(1); CP_COMMIT();

    // stage Q, build per-warp Q fragments (hi + lo resident)
#pragma unroll
    for (int it = 0; it < 4; it++) {
        const int r = it * 32 + ldr;
        const size_t g = (size_t)(q0 + r) * HD + ldc;
        *(uint4*)&sQh[r * FQ + ldc] = *(const uint4*)(Qh + g);
        *(uint4*)&sQl[r * FQ + ldc] = *(const uint4*)(Ql + g);
    }
    __syncthreads();
    uint32_t qf[2][4][4];
    {
        const int qrow = w * 16 + (lane & 15);
#pragma unroll
        for (int kc = 0; kc < 4; kc++) {
            const int col = kc * 16 + 8 * (lane >> 4);
            ldsm4(qf[0][kc][0], qf[0][kc][1], qf[0][kc][2], qf[0][kc][3],
                  smem_u32(&sQh[qrow * FQ + col]));
            ldsm4(qf[1][kc][0], qf[1][kc][1], qf[1][kc][2], qf[1][kc][3],
                  smem_u32(&sQl[qrow * FQ + col]));
        }
    }

    float o[8][4];
#pragma unroll
    for (int nt = 0; nt < 8; nt++)
#pragma unroll
        for (int j = 0; j < 4; j++) o[nt][j] = 0.f;
    float mrow[2] = {-1e30f, -1e30f};
    float lrow[2] = {0.f, 0.f};

    for (int kt = 0; kt < ntiles; kt++) {
        const int k0 = kt * 64;
        CP_WAIT1();
        __syncthreads();
        if (kt + 2 < ntiles) prefetch_kv(kt + 2);
        CP_COMMIT();
        const uint32_t sb = sbase + (kt % 3) * F_STAGE;

        // S = Q K^T  (log2-domain logits: Q pre-scaled by 1/8*log2e)
        float s[8][4];
#pragma unroll
        for (int nt = 0; nt < 8; nt++)
#pragma unroll
            for (int j = 0; j < 4; j++) s[nt][j] = 0.f;

        const int brow_base = ((lane >> 4) << 3) + (lane & 7);
#pragma unroll
        for (int kc = 0; kc < 4; kc++) {
            const int bcol = kc * 16 + ((lane >> 3) & 1) * 8;
#pragma unroll
            for (int p = 0; p < 4; p++) {
                const uint32_t kd = sb + ((brow_base + p * 16) * FQ + bcol) * 2;
                uint32_t h0, h1, h2, h3, l0, l1, l2, l3;
                ldsm4(h0, h1, h2, h3, kd);
                ldsm4(l0, l1, l2, l3, kd + F_KBYTES);
                mma16816(s[2 * p],     qf[0][kc], h0, h1);
                mma16816(s[2 * p],     qf[1][kc], h0, h1);
                mma16816(s[2 * p],     qf[0][kc], l0, l1);
                mma16816(s[2 * p + 1], qf[0][kc], h2, h3);
                mma16816(s[2 * p + 1], qf[1][kc], h2, h3);
                mma16816(s[2 * p + 1], qf[0][kc], l2, l3);
            }
        }

        // causal mask on the diagonal band
        if (kt >= 2 * qi) {
#pragma unroll
            for (int nt = 0; nt < 8; nt++)
#pragma unroll
                for (int j = 0; j < 4; j++) {
                    const int gr = q0 + w * 16 + (lane >> 2) + (j >> 1) * 8;
                    const int gc = k0 + nt * 8 + (lane & 3) * 2 + (j & 1);
                    if (gc > gr) s[nt][j] = -1e30f;
                }
        }

        // online softmax in exp2 domain
#pragma unroll
        for (int h = 0; h < 2; h++) {
            float mx = -1e30f;
#pragma unroll
            for (int nt = 0; nt < 8; nt++)
                mx = fmaxf(mx, fmaxf(s[nt][2 * h], s[nt][2 * h + 1]));
            mx = fmaxf(mx, __shfl_xor_sync(0xffffffffu, mx, 1));
            mx = fmaxf(mx, __shfl_xor_sync(0xffffffffu, mx, 2));
            const float mnew = fmaxf(mrow[h], mx);
            const float alpha = ex2f(mrow[h] - mnew);
            float sum = 0.f;
#pragma unroll
            for (int nt = 0; nt < 8; nt++) {
                float e0 = ex2f(s[nt][2 * h]     - mnew);
                float e1 = ex2f(s[nt][2 * h + 1] - mnew);
                s[nt][2 * h] = e0; s[nt][2 * h + 1] = e1;
                sum += e0 + e1;
            }
            sum += __shfl_xor_sync(0xffffffffu, sum, 1);
            sum += __shfl_xor_sync(0xffffffffu, sum, 2);
            lrow[h] = lrow[h] * alpha + sum;
            mrow[h] = mnew;
#pragma unroll
            for (int nt = 0; nt < 8; nt++) {
                o[nt][2 * h] *= alpha; o[nt][2 * h + 1] *= alpha;
            }
        }

        // O += P V
        const int vcol_base = (lane >> 4) << 3;
        const int vrow_base = (lane & 7) + ((lane >> 3) & 1) * 8;
#pragma unroll
        for (int kc = 0; kc < 4; kc++) {
            uint32_t ph[4], pl[4];
            {
                const float* c0 = s[2 * kc];
                const float* c1 = s[2 * kc + 1];
                __nv_bfloat162 t0 = __floats2bfloat162_rn(c0[0], c0[1]);
                __nv_bfloat162 t1 = __floats2bfloat162_rn(c0[2], c0[3]);
                __nv_bfloat162 t2 = __floats2bfloat162_rn(c1[0], c1[1]);
                __nv_bfloat162 t3 = __floats2bfloat162_rn(c1[2], c1[3]);
                ph[0] = *(uint32_t*)&t0; ph[1] = *(uint32_t*)&t1;
                ph[2] = *(uint32_t*)&t2; ph[3] = *(uint32_t*)&t3;
                __nv_bfloat162 u0 = __floats2bfloat162_rn(
                    c0[0] - __bfloat162float(t0.x), c0[1] - __bfloat162float(t0.y));
                __nv_bfloat162 u1 = __floats2bfloat162_rn(
                    c0[2] - __bfloat162float(t1.x), c0[3] - __bfloat162float(t1.y));
                __nv_bfloat162 u2 = __floats2bfloat162_rn(
                    c1[0] - __bfloat162float(t2.x), c1[1] - __bfloat162float(t2.y));
                __nv_bfloat162 u3 = __floats2bfloat162_rn(
                    c1[2] - __bfloat162float(t3.x), c1[3] - __bfloat162float(t3.y));
                pl[0] = *(uint32_t*)&u0; pl[1] = *(uint32_t*)&u1;
                pl[2] = *(uint32_t*)&u2; pl[3] = *(uint32_t*)&u3;
            }
            const int vrow = kc * 16 + vrow_base;
#pragma unroll
            for (int p = 0; p < 4; p++) {
                const uint32_t vd =
                    sb + 2 * F_KBYTES + (vrow * FQ + p * 16 + vcol_base) * 2;
                uint32_t h0, h1, h2, h3, l0, l1, l2, l3;
                ldsm4t(h0, h1, h2, h3, vd);
                ldsm4t(l0, l1, l2, l3, vd + F_KBYTES);
                mma16816(o[2 * p],     ph, h0, h1);
                mma16816(o[2 * p],     pl, h0, h1);
                mma16816(o[2 * p],     ph, l0, l1);
                mma16816(o[2 * p + 1], ph, h2, h3);
                mma16816(o[2 * p + 1], pl, h2, h3);
                mma16816(o[2 * p + 1], ph, l2, l3);
            }
        }
    }

    // epilogue
    const int b = bh >> 4;
    const int hh = bh & 15;
    const float inv0 = 1.0f / lrow[0];
    const float inv1 = 1.0f / lrow[1];
    const int t0 = q0 + w * 16 + (lane >> 2);
#pragma unroll
    for (int nt = 0; nt < 8; nt++) {
        const int d = nt * 8 + (lane & 3) * 2;
        {
            float f0 = o[nt][0] * inv0, f1 = o[nt][1] * inv0;
            __nv_bfloat162 hi2 = __floats2bfloat162_rn(f0, f1);
            __nv_bfloat162 lo2 = __floats2bfloat162_rn(
                f0 - __bfloat162float(hi2.x), f1 - __bfloat162float(hi2.y));
            const size_t off = ((size_t)(b * T_SEQ + t0)) * CH + hh * HD + d;
            *(__nv_bfloat162*)&g_at_hi[off] = hi2;
            *(__nv_bfloat162*)&g_at_lo[off] = lo2;
        }
        {
            float f0 = o[nt][2] * inv1, f1 = o[nt][3] * inv1;
            __nv_bfloat162 hi2 = __floats2bfloat162_rn(f0, f1);
            __nv_bfloat162 lo2 = __floats2bfloat162_rn(
                f0 - __bfloat162float(hi2.x), f1 - __bfloat162float(hi2.y));
            const size_t off = ((size_t)(b * T_SEQ + t0 + 8)) * CH + hh * HD + d;
            *(__nv_bfloat162*)&g_at_hi[off] = hi2;
            *(__nv_bfloat162*)&g_at_lo[off] = lo2;
        }
    }
}

// ---------------------------------------------------------------------------
// Launch. Motif conv branch (d_in[3], d_in[4]) is mathematically a no-op:
// its bias is constant along the softmax reduction axis, so softmax cancels it.
// ---------------------------------------------------------------------------
extern "C" void kernel_launch(void* const* d_in, const int* in_sizes, int n_in,
                              void* d_out, int out_size)
{
    (void)in_sizes; (void)n_in; (void)out_size;
    const float* x    = (const float*)d_in[0];
    const float* Wqkv = (const float*)d_in[1];
    const float* bqkv = (const float*)d_in[2];
    const float* Wout = (const float*)d_in[5];
    const float* bout = (const float*)d_in[6];
    float* out = (float*)d_out;

    cudaFuncSetAttribute(gemm_mma,
                         cudaFuncAttributeMaxDynamicSharedMemorySize, GEMM_SMEM);
    cudaFuncSetAttribute(flash_mma,
                         cudaFuncAttributeMaxDynamicSharedMemorySize, FLASH_SMEM);

    bf16 *xh, *xl, *wqh, *wql, *woh, *wol, *ath, *atl;
    cudaGetSymbolAddress((void**)&xh,  g_x_hi);
    cudaGetSymbolAddress((void**)&xl,  g_x_lo);
    cudaGetSymbolAddress((void**)&wqh, g_wq_hi);
    cudaGetSymbolAddress((void**)&wql, g_wq_lo);
    cudaGetSymbolAddress((void**)&woh, g_wo_hi);
    cudaGetSymbolAddress((void**)&wol, g_wo_lo);
    cudaGetSymbolAddress((void**)&ath, g_at_hi);
    cudaGetSymbolAddress((void**)&atl, g_at_lo);

    convert_split<<<BT * CH / 1024, 256>>>(x, xh, xl, BT * CH);
    convert_split<<<3 * CH * CH / 1024, 256>>>(Wqkv, wqh, wql, 3 * CH * CH);
    convert_split<<<CH * CH / 1024, 256>>>(Wout, woh, wol, CH * CH);

    // QKV projection -> g_qkv (bf16 hi/lo, Q pre-scaled by 0.125*log2e)
    gemm_mma<<<dim3(3 * CH / 64, BT / 128), 256, GEMM_SMEM>>>(
        xh, xl, wqh, wql, bqkv, nullptr, 3 * CH, CH, 0);

    // flash causal attention -> g_at (bf16 hi/lo)
    flash_mma<<<dim3(T_SEQ / 128, BHCNT), 256, FLASH_SMEM>>>();

    // output projection -> d_out (fp32)
    gemm_mma<<<dim3(CH / 64, BT / 128), 256, GEMM_SMEM>>>(
        ath, atl, woh, wol, bout, out, CH, CH, 1);
}